// round 7
// baseline (speedup 1.0000x reference)
#include <cuda_runtime.h>
#include <cuda_bf16.h>
#include <math.h>

constexpr int N  = 8388608;              // 2^23 samples (fixed by reference)
constexpr int NK = 8388608;              // 2^23 achievable uniform grid points
constexpr int BSHIFT = 6;                // 64 grid points per bucket
constexpr int NB = NK >> BSHIFT;         // 131072 buckets

constexpr int P_TPB    = 256;
constexpr int P_IPT    = 8;
constexpr int P_BLOCKS = N / (P_TPB * P_IPT);          // 4096

constexpr int S_TPB    = 256;
constexpr int S_BPT    = 2;                            // buckets per thread (1 float4)
constexpr int S_TILE   = S_TPB * S_BPT;                // 512 buckets per block
constexpr int S_BLOCKS = NB / S_TILE;                  // 256

// ---------------- static device scratch ------------------------------------
__device__ float2 g_hist[NB];             // {sum exp(s), event count}  (1 MB, zero-init;
                                          //  scan_k3 re-zeroes it every call)
__device__ double g_bsums[S_BLOCKS];      // per-scan-block exp-sum totals
__device__ double g_part1[P_BLOCKS];      // pass1: per-block -sum(e*s)
__device__ double g_part2[S_BLOCKS];      // scan_k3: weighted-log partials

// Coarse bucket: float estimate of k is within ~1.5 grid points of exact;
// with 64-wide buckets boundary misassignment is the same order as the
// (validated) tie approximation.
__device__ __forceinline__ int bucket_of(float t) {
    int k = __float2int_rn(t * 83886.08f);              // t * 2^23 / 100
    k = max(0, min(k, NK - 1));
    return (NK - 1 - k) >> BSHIFT;                      // ascending = desc time
}

// One 8-byte vector reduction: hist[b] += {ex, ev}
__device__ __forceinline__ void red_v2(float2* addr, float ex, float ev) {
    asm volatile("red.global.add.v2.f32 [%0], {%1, %2};"
                 :: "l"(addr), "f"(ex), "f"(ev) : "memory");
}

// Pass 1: histogram {exp(s), e} via 8-byte REDs + in-register fp64 -sum(e*s).
__global__ __launch_bounds__(P_TPB) void
pass1_kernel(const float* __restrict__ truth,
             const float* __restrict__ scores,
             float2* __restrict__ hist,
             double* __restrict__ part1) {
    int base = (blockIdx.x * P_TPB + threadIdx.x) * P_IPT;
    float4 s0 = *reinterpret_cast<const float4*>(scores + base);
    float4 s1 = *reinterpret_cast<const float4*>(scores + base + 4);
    float4 t0 = *reinterpret_cast<const float4*>(truth + 2 * base);       // e t e t
    float4 t1 = *reinterpret_cast<const float4*>(truth + 2 * base + 4);
    float4 t2 = *reinterpret_cast<const float4*>(truth + 2 * base + 8);
    float4 t3 = *reinterpret_cast<const float4*>(truth + 2 * base + 12);

    float ev[8] = {t0.x, t0.z, t1.x, t1.z, t2.x, t2.z, t3.x, t3.z};
    float tm[8] = {t0.y, t0.w, t1.y, t1.w, t2.y, t2.w, t3.y, t3.w};
    float sc[8] = {s0.x, s0.y, s0.z, s0.w, s1.x, s1.y, s1.z, s1.w};

    double acc = 0.0;
    #pragma unroll
    for (int j = 0; j < 8; ++j) {
        int   b  = bucket_of(tm[j]);
        float ex = __expf(sc[j]);
        red_v2(&hist[b], ex, ev[j]);                    // ev is exactly 0 or 1
        acc = fma(-(double)ev[j], (double)sc[j], acc);
    }

    __shared__ double sh[P_TPB];
    sh[threadIdx.x] = acc;
    __syncthreads();
    for (int s = P_TPB / 2; s > 0; s >>= 1) {
        if (threadIdx.x < s) sh[threadIdx.x] += sh[threadIdx.x + s];
        __syncthreads();
    }
    if (threadIdx.x == 0) part1[blockIdx.x] = sh[0];
}

// Scan stage 1: per-block fp64 sums of bucket exp-sums (1 float4 = 2 buckets).
__global__ __launch_bounds__(S_TPB) void
scan_k1(const float2* __restrict__ hist, double* __restrict__ bsums) {
    __shared__ double sh[S_TPB];
    int base = blockIdx.x * S_TILE + threadIdx.x * S_BPT;
    float4 h = *reinterpret_cast<const float4*>(hist + base);
    sh[threadIdx.x] = (double)h.x + (double)h.z;
    __syncthreads();
    for (int s = S_TPB / 2; s > 0; s >>= 1) {
        if (threadIdx.x < s) sh[threadIdx.x] += sh[threadIdx.x + s];
        __syncthreads();
    }
    if (threadIdx.x == 0) bsums[blockIdx.x] = sh[0];
}

// Scan stage 2: exclusive scan of the 256 block sums (single block).
__global__ void scan_k2(double* __restrict__ bsums) {
    __shared__ double sh[S_BLOCKS];
    int tid = threadIdx.x;
    sh[tid] = bsums[tid];
    __syncthreads();
    for (int off = 1; off < S_BLOCKS; off <<= 1) {
        double v = (tid >= off) ? sh[tid - off] : 0.0;
        __syncthreads();
        sh[tid] += v;
        __syncthreads();
    }
    bsums[tid] = (tid == 0) ? 0.0 : sh[tid - 1];
}

// Scan stage 3: block-local prefix + midpoint-weighted event log, then zero the
// histogram for the next graph replay (replaces the up-front memset).
__global__ __launch_bounds__(S_TPB) void
scan_k3(float2* __restrict__ hist,
        const double* __restrict__ bsums,
        double* __restrict__ part2) {
    __shared__ double sh[S_TPB];
    int tid  = threadIdx.x;
    int base = blockIdx.x * S_TILE + tid * S_BPT;

    float4 h = *reinterpret_cast<const float4*>(hist + base);
    float S0 = h.x, C0 = h.y, S1 = h.z, C1 = h.w;

    sh[tid] = (double)S0 + (double)S1;
    __syncthreads();
    for (int off = 1; off < S_TPB; off <<= 1) {
        double v = (tid >= off) ? sh[tid - off] : 0.0;
        __syncthreads();
        sh[tid] += v;
        __syncthreads();
    }
    double excl = bsums[blockIdx.x] + ((tid == 0) ? 0.0 : sh[tid - 1]);

    double acc = 0.0;
    if (C0 != 0.0f)
        acc += (double)C0 * (double)logf((float)(excl + 0.5 * (double)S0));
    excl += (double)S0;
    if (C1 != 0.0f)
        acc += (double)C1 * (double)logf((float)(excl + 0.5 * (double)S1));

    // zero the histogram for the next replay (read already done)
    *reinterpret_cast<float4*>(hist + base) = make_float4(0.f, 0.f, 0.f, 0.f);

    __syncthreads();
    sh[tid] = acc;
    __syncthreads();
    for (int s = S_TPB / 2; s > 0; s >>= 1) {
        if (tid < s) sh[tid] += sh[tid + s];
        __syncthreads();
    }
    if (tid == 0) part2[blockIdx.x] = sh[0];
}

// Final: reduce pass1 partials + scan_k3 partials, divide by N.
__global__ __launch_bounds__(1024) void
finalize_kernel(const double* __restrict__ part1,
                const double* __restrict__ part2,
                float* __restrict__ out) {
    __shared__ double sh[1024];
    int tid = threadIdx.x;
    double v = 0.0;
    for (int i = tid; i < P_BLOCKS; i += 1024) v += part1[i];
    if (tid < S_BLOCKS) v += part2[tid];
    sh[tid] = v;
    __syncthreads();
    for (int s = 512; s > 0; s >>= 1) {
        if (tid < s) sh[tid] += sh[tid + s];
        __syncthreads();
    }
    if (tid == 0) out[0] = (float)(sh[0] / (double)N);
}

extern "C" void kernel_launch(void* const* d_in, const int* in_sizes, int n_in,
                              void* d_out, int out_size) {
    const float* scores;
    const float* truth;
    if (in_sizes[0] == N) {
        scores = (const float*)d_in[0];
        truth  = (const float*)d_in[1];
    } else {
        scores = (const float*)d_in[1];
        truth  = (const float*)d_in[0];
    }
    float* out = (float*)d_out;

    float2* hist;
    double *bsums, *p1, *p2;
    cudaGetSymbolAddress((void**)&hist,  g_hist);
    cudaGetSymbolAddress((void**)&bsums, g_bsums);
    cudaGetSymbolAddress((void**)&p1,    g_part1);
    cudaGetSymbolAddress((void**)&p2,    g_part2);

    // hist is zero on entry: zero-initialized statically, and scan_k3 re-zeroes
    // it at the end of every call (stream order guarantees no race).
    pass1_kernel<<<P_BLOCKS, P_TPB>>>(truth, scores, hist, p1);
    scan_k1<<<S_BLOCKS, S_TPB>>>(hist, bsums);
    scan_k2<<<1, S_BLOCKS>>>(bsums);
    scan_k3<<<S_BLOCKS, S_TPB>>>(hist, bsums, p2);
    finalize_kernel<<<1, 1024>>>(p1, p2, out);
}

// round 8
// speedup vs baseline: 1.3202x; 1.3202x over previous
#include <cuda_runtime.h>
#include <cuda_bf16.h>
#include <math.h>

constexpr int N  = 8388608;              // 2^23 samples (fixed by reference)
constexpr int NK = 8388608;              // 2^23 achievable uniform grid points
constexpr int BSHIFT = 6;                // 64 grid points per bucket
constexpr int NB = NK >> BSHIFT;         // 131072 buckets

constexpr int P_TPB    = 256;
constexpr int P_IPT    = 8;
constexpr int P_BLOCKS = N / (P_TPB * P_IPT);          // 4096

constexpr int S_TPB    = 256;
constexpr int S_BPT    = 2;                            // buckets per thread
constexpr int S_TILE   = S_TPB * S_BPT;                // 512 buckets per block
constexpr int S_BLOCKS = NB / S_TILE;                  // 256

// ---------------- static device scratch ------------------------------------
// 16-byte stride per bucket is load-bearing: 8-byte-stride buckets share L2
// chunks and neighbor-bucket REDs serialize (R7 regression, +20us).
__device__ float4 g_hist[NB];            // {sum exp(s), sum e, sum e*s, 0} (2 MB,
                                         //  zero-init; scan_k3 re-zeroes each call)
__device__ double g_bsums[S_BLOCKS];     // per-scan-block exp-sum totals
__device__ double g_part2[S_BLOCKS];     // scan_k3 partials

__device__ __forceinline__ int bucket_of(float t) {
    int k = __float2int_rn(t * 83886.08f);              // t * 2^23 / 100
    k = max(0, min(k, NK - 1));
    return (NK - 1 - k) >> BSHIFT;                      // ascending = desc time
}

// One 16-byte vector reduction: hist[b] += {ex, ev, ev*s, 0}
__device__ __forceinline__ void red_v4(float4* addr, float ex, float ev, float es) {
    asm volatile("red.global.add.v4.f32 [%0], {%1, %2, %3, %4};"
                 :: "l"(addr), "f"(ex), "f"(ev), "f"(es), "f"(0.0f) : "memory");
}

// Pass 1: pure load -> compute -> RED (at the REDG spread-address floor).
__global__ __launch_bounds__(P_TPB) void
pass1_kernel(const float* __restrict__ truth,
             const float* __restrict__ scores,
             float4* __restrict__ hist) {
    int base = (blockIdx.x * P_TPB + threadIdx.x) * P_IPT;
    float4 s0 = *reinterpret_cast<const float4*>(scores + base);
    float4 s1 = *reinterpret_cast<const float4*>(scores + base + 4);
    float4 t0 = *reinterpret_cast<const float4*>(truth + 2 * base);       // e t e t
    float4 t1 = *reinterpret_cast<const float4*>(truth + 2 * base + 4);
    float4 t2 = *reinterpret_cast<const float4*>(truth + 2 * base + 8);
    float4 t3 = *reinterpret_cast<const float4*>(truth + 2 * base + 12);

    float ev[8] = {t0.x, t0.z, t1.x, t1.z, t2.x, t2.z, t3.x, t3.z};
    float tm[8] = {t0.y, t0.w, t1.y, t1.w, t2.y, t2.w, t3.y, t3.w};
    float sc[8] = {s0.x, s0.y, s0.z, s0.w, s1.x, s1.y, s1.z, s1.w};

    #pragma unroll
    for (int j = 0; j < 8; ++j) {
        int   b  = bucket_of(tm[j]);
        float ex = __expf(sc[j]);
        red_v4(&hist[b], ex, ev[j], ev[j] * sc[j]);     // ev is exactly 0 or 1
    }
}

// ---- warp helpers (fp64 shuffles are native) -------------------------------
__device__ __forceinline__ double warp_incl_scan(double v) {
    #pragma unroll
    for (int d = 1; d < 32; d <<= 1) {
        double u = __shfl_up_sync(0xffffffffu, v, d);
        if ((threadIdx.x & 31) >= d) v += u;
    }
    return v;
}
__device__ __forceinline__ double warp_reduce(double v) {
    #pragma unroll
    for (int d = 16; d > 0; d >>= 1)
        v += __shfl_down_sync(0xffffffffu, v, d);
    return v;
}

// Scan stage 1: per-block fp64 sums of bucket exp-sums.
__global__ __launch_bounds__(S_TPB) void
scan_k1(const float4* __restrict__ hist, double* __restrict__ bsums) {
    __shared__ double wsum[S_TPB / 32];
    int tid  = threadIdx.x;
    int base = blockIdx.x * S_TILE + tid * S_BPT;
    double v = (double)hist[base].x + (double)hist[base + 1].x;
    v = warp_reduce(v);
    if ((tid & 31) == 0) wsum[tid >> 5] = v;
    __syncthreads();
    if (tid < 32) {
        double w = (tid < S_TPB / 32) ? wsum[tid] : 0.0;
        w = warp_reduce(w);
        if (tid == 0) bsums[blockIdx.x] = w;
    }
}

// Scan stage 2: exclusive scan of the 256 block sums (one block, shuffles).
__global__ __launch_bounds__(S_BLOCKS) void
scan_k2(double* __restrict__ bsums) {
    __shared__ double wsum[S_BLOCKS / 32];
    int tid = threadIdx.x;
    double v   = bsums[tid];
    double inc = warp_incl_scan(v);
    if ((tid & 31) == 31) wsum[tid >> 5] = inc;
    __syncthreads();
    if (tid < 32) {
        double w = (tid < S_BLOCKS / 32) ? wsum[tid] : 0.0;
        double wi = warp_incl_scan(w);
        if (tid < S_BLOCKS / 32) wsum[tid] = wi - w;    // exclusive warp offset
    }
    __syncthreads();
    bsums[tid] = wsum[tid >> 5] + inc - v;              // exclusive
}

// Scan stage 3: block-local prefix (shuffle scan), midpoint-weighted event log
// minus sum(e*s), then zero the histogram for the next replay.
__global__ __launch_bounds__(S_TPB) void
scan_k3(float4* __restrict__ hist,
        const double* __restrict__ bsums,
        double* __restrict__ part2) {
    __shared__ double wsum[S_TPB / 32];
    int tid  = threadIdx.x;
    int lane = tid & 31;
    int wid  = tid >> 5;
    int base = blockIdx.x * S_TILE + tid * S_BPT;

    float4 h0 = hist[base];
    float4 h1 = hist[base + 1];

    double tsum = (double)h0.x + (double)h1.x;
    double inc  = warp_incl_scan(tsum);
    if (lane == 31) wsum[wid] = inc;
    __syncthreads();
    if (tid < 32) {
        double w  = (tid < S_TPB / 32) ? wsum[tid] : 0.0;
        double wi = warp_incl_scan(w);
        if (tid < S_TPB / 32) wsum[tid] = wi - w;       // exclusive warp offset
    }
    __syncthreads();
    double excl = bsums[blockIdx.x] + wsum[wid] + (inc - tsum);

    double acc = 0.0;
    if (h0.y != 0.0f)
        acc += (double)h0.y * (double)logf((float)(excl + 0.5 * (double)h0.x));
    acc -= (double)h0.z;
    excl += (double)h0.x;
    if (h1.y != 0.0f)
        acc += (double)h1.y * (double)logf((float)(excl + 0.5 * (double)h1.x));
    acc -= (double)h1.z;

    // zero the histogram for the next replay (read already done)
    float4 z = make_float4(0.f, 0.f, 0.f, 0.f);
    hist[base]     = z;
    hist[base + 1] = z;

    acc = warp_reduce(acc);
    __syncthreads();
    if (lane == 0) wsum[wid] = acc;
    __syncthreads();
    if (tid < 32) {
        double w = (tid < S_TPB / 32) ? wsum[tid] : 0.0;
        w = warp_reduce(w);
        if (tid == 0) part2[blockIdx.x] = w;
    }
}

// Final: reduce 256 partials, divide by N.
__global__ __launch_bounds__(S_BLOCKS) void
finalize_kernel(const double* __restrict__ part2, float* __restrict__ out) {
    __shared__ double wsum[S_BLOCKS / 32];
    int tid = threadIdx.x;
    double v = warp_reduce(part2[tid]);
    if ((tid & 31) == 0) wsum[tid >> 5] = v;
    __syncthreads();
    if (tid < 32) {
        double w = (tid < S_BLOCKS / 32) ? wsum[tid] : 0.0;
        w = warp_reduce(w);
        if (tid == 0) out[0] = (float)(w / (double)N);
    }
}

extern "C" void kernel_launch(void* const* d_in, const int* in_sizes, int n_in,
                              void* d_out, int out_size) {
    const float* scores;
    const float* truth;
    if (in_sizes[0] == N) {
        scores = (const float*)d_in[0];
        truth  = (const float*)d_in[1];
    } else {
        scores = (const float*)d_in[1];
        truth  = (const float*)d_in[0];
    }
    float* out = (float*)d_out;

    float4* hist;
    double *bsums, *p2;
    cudaGetSymbolAddress((void**)&hist,  g_hist);
    cudaGetSymbolAddress((void**)&bsums, g_bsums);
    cudaGetSymbolAddress((void**)&p2,    g_part2);

    // hist is zero on entry: zero-initialized statically, and scan_k3 re-zeroes
    // it at the end of every call (stream order guarantees no race).
    pass1_kernel<<<P_BLOCKS, P_TPB>>>(truth, scores, hist);
    scan_k1<<<S_BLOCKS, S_TPB>>>(hist, bsums);
    scan_k2<<<1, S_BLOCKS>>>(bsums);
    scan_k3<<<S_BLOCKS, S_TPB>>>(hist, bsums, p2);
    finalize_kernel<<<1, S_BLOCKS>>>(p2, out);
}